// round 8
// baseline (speedup 1.0000x reference)
#include <cuda_runtime.h>
#include <cstdint>
#include <cstddef>

// Problem shape (fixed)
#define Bc 2
#define Hc 16
#define Sc 2048
#define Dc 64

// Tiling
#define BM 128            // q rows per CTA
#define BK 64             // keys per tile
#define NT (Sc / BK)      // 32 tiles
#define KP 68             // q/k smem pitch (words); 68%32==4 -> conflict-free ldmatrix
#define VP 72             // v smem pitch   (words); 72%32==8 -> conflict-free B loads

// SMEM byte offsets
#define SM_Q   0
#define SM_K0  (BM * KP * 4)              // 34816
#define SM_K1  (SM_K0 + BK * KP * 4)      // 52224
#define SM_V0  (SM_K1 + BK * KP * 4)      // 69632
#define SM_V1  (SM_V0 + BK * VP * 4)      // 88064
#define SM_TOT (SM_V1 + BK * VP * 4)      // 106496

static __device__ __forceinline__ uint32_t smem_u32(const void* p) {
    uint32_t a;
    asm("{ .reg .u64 t; cvta.to.shared.u64 t, %1; cvt.u32.u64 %0, t; }"
        : "=r"(a) : "l"(p));
    return a;
}
static __device__ __forceinline__ uint32_t f2tf32(float f) {
    uint32_t u;
    asm("cvt.rna.tf32.f32 %0, %1;" : "=r"(u) : "f"(f));
    return u;
}
static __device__ __forceinline__ void mma_tf32(float c[4],
                                                uint32_t a0, uint32_t a1, uint32_t a2, uint32_t a3,
                                                uint32_t b0, uint32_t b1) {
    asm volatile(
        "mma.sync.aligned.m16n8k8.row.col.f32.tf32.tf32.f32 "
        "{%0,%1,%2,%3}, {%4,%5,%6,%7}, {%8,%9}, {%0,%1,%2,%3};"
        : "+f"(c[0]), "+f"(c[1]), "+f"(c[2]), "+f"(c[3])
        : "r"(a0), "r"(a1), "r"(a2), "r"(a3), "r"(b0), "r"(b1));
}
static __device__ __forceinline__ void ldsm4(uint32_t& r0, uint32_t& r1,
                                             uint32_t& r2, uint32_t& r3, uint32_t a) {
    asm volatile("ldmatrix.sync.aligned.m8n8.x4.shared.b16 {%0,%1,%2,%3}, [%4];"
                 : "=r"(r0), "=r"(r1), "=r"(r2), "=r"(r3) : "r"(a));
}

__global__ __launch_bounds__(256, 2)
void fra_mma5_kernel(const float* __restrict__ q,
                     const float* __restrict__ k,
                     const float* __restrict__ v,
                     const float* __restrict__ mask,
                     float* __restrict__ o)
{
    extern __shared__ char smem[];
    const uint32_t sb = smem_u32(smem);
    const int tid  = threadIdx.x;
    const int lane = tid & 31;
    const int wid  = tid >> 5;
    const int gid  = lane >> 2;
    const int tig  = lane & 3;
    const int mbase = wid * 16;            // warp's 16-row strip
    const int bh = blockIdx.y;
    const int q0 = blockIdx.x * BM;

    const float* qg = q    + (size_t)bh * Sc * Dc;
    const float* kg = k    + (size_t)bh * Sc * Dc;
    const float* vg = v    + (size_t)bh * Sc * Dc;
    const float* mg = mask + (size_t)bh * Sc * Sc;
    float*       og = o    + (size_t)bh * Sc * Dc;

    // per-thread staging coordinates (same for K and V)
    const int sr  = tid >> 4;            // base row 0..15 (rows sr, sr+16, sr+32, sr+48)
    const int sc4 = (tid & 15) * 4;      // col 0,4,...,60

    // ---- stage Q once (tf32, pitched) ----
    #pragma unroll
    for (int i = 0; i < 8; i++) {
        int fi = tid + i * 256;
        int r = fi >> 4, c4 = (fi & 15) * 4;
        float4 x = *(const float4*)(qg + (size_t)(q0 + r) * Dc + c4);
        uint4 y;
        y.x = f2tf32(x.x); y.y = f2tf32(x.y); y.z = f2tf32(x.z); y.w = f2tf32(x.w);
        *(uint4*)(smem + SM_Q + (size_t)(r * KP + c4) * 4) = y;
    }
    // ---- prologue: stage K/V tile 0 into buffer 0 ----
    #pragma unroll
    for (int i = 0; i < 4; i++) {
        int r = sr + i * 16;
        float4 xk = *(const float4*)(kg + (size_t)r * Dc + sc4);
        float4 xv = *(const float4*)(vg + (size_t)r * Dc + sc4);
        uint4 yk, yv;
        yk.x = f2tf32(xk.x); yk.y = f2tf32(xk.y); yk.z = f2tf32(xk.z); yk.w = f2tf32(xk.w);
        yv.x = f2tf32(xv.x); yv.y = f2tf32(xv.y); yv.z = f2tf32(xv.z); yv.w = f2tf32(xv.w);
        *(uint4*)(smem + SM_K0 + (size_t)(r * KP + sc4) * 4) = yk;
        *(uint4*)(smem + SM_V0 + (size_t)(r * VP + sc4) * 4) = yv;
    }
    __syncthreads();

    // per-thread ldmatrix address components (PTX shared-space operands only)
    const int lrow = (lane & 7) + 8 * ((lane >> 3) & 1);
    const int lcol = 4 * (lane >> 4);
    const uint32_t aAddr0 = sb + SM_Q + (uint32_t)((mbase + lrow) * KP + lcol) * 4;

    float oacc[8][4];
    #pragma unroll
    for (int d = 0; d < 8; d++)
        #pragma unroll
        for (int r = 0; r < 4; r++) oacc[d][r] = 0.0f;
    float racc0 = 0.0f, racc1 = 0.0f;

    const float* mr0 = mg + (size_t)(q0 + mbase + gid) * Sc;
    const float* mr1 = mr0 + (size_t)8 * Sc;

    const int s0l = tig >> 1;
    const int s2l = s0l + 2;
    const bool od = (tig & 1) != 0;

    for (int tt = 0; tt < NT; tt++) {
        const int t = tt * BK;
        const bool pf = (tt + 1 < NT);
        const uint32_t kb   = sb + ((tt & 1) ? SM_K1 : SM_K0);       // ldmatrix operand
        const uint32_t* vsW = (const uint32_t*)(smem + ((tt & 1) ? SM_V1 : SM_V0));
        char* nk = smem + ((tt & 1) ? SM_K0 : SM_K1);                 // generic for STS
        char* nv = smem + ((tt & 1) ? SM_V0 : SM_V1);

        // ---- issue next-K LDGs (latency hidden under GEMM1) ----
        float4 xk[4];
        if (pf) {
            #pragma unroll
            for (int i = 0; i < 4; i++)
                xk[i] = *(const float4*)(kg + (size_t)(t + BK + sr + i * 16) * Dc + sc4);
        }

        // ---- GEMM1: S(16x64) = Q @ K^T (frags already tf32) ----
        float sacc[8][4];
        #pragma unroll
        for (int j = 0; j < 8; j++)
            #pragma unroll
            for (int r = 0; r < 4; r++) sacc[j][r] = 0.0f;

        #pragma unroll
        for (int s = 0; s < 8; s++) {
            uint32_t a0, a1, a2, a3;
            ldsm4(a0, a1, a2, a3, aAddr0 + (uint32_t)s * 32);
            #pragma unroll
            for (int p = 0; p < 4; p++) {
                uint32_t t0, t1, t2, t3;
                ldsm4(t0, t1, t2, t3,
                      kb + (uint32_t)((16 * p + lrow) * KP + 8 * s + lcol) * 4);
                mma_tf32(sacc[2 * p],     a0, a1, a2, a3, t0, t2);
                mma_tf32(sacc[2 * p + 1], a0, a1, a2, a3, t1, t3);
            }
        }

        // ---- store next-K (cvt once), then issue next-V LDGs ----
        float4 xv[4];
        if (pf) {
            #pragma unroll
            for (int i = 0; i < 4; i++) {
                uint4 y;
                y.x = f2tf32(xk[i].x); y.y = f2tf32(xk[i].y);
                y.z = f2tf32(xk[i].z); y.w = f2tf32(xk[i].w);
                *(uint4*)(nk + (size_t)((sr + i * 16) * KP + sc4) * 4) = y;
            }
            #pragma unroll
            for (int i = 0; i < 4; i++)
                xv[i] = *(const float4*)(vg + (size_t)(t + BK + sr + i * 16) * Dc + sc4);
        }

        // ---- per key-group: mask, abs-sum, permute -> A frag, GEMM2 ----
        float2 m0 = *(const float2*)(mr0 + t + 2 * tig);
        float2 m1 = *(const float2*)(mr1 + t + 2 * tig);
        #pragma unroll
        for (int j = 0; j < 8; j++) {
            float2 n0 = m0, n1 = m1;
            if (j < 7) {
                n0 = *(const float2*)(mr0 + t + 8 * (j + 1) + 2 * tig);
                n1 = *(const float2*)(mr1 + t + 8 * (j + 1) + 2 * tig);
            }
            float c0 = sacc[j][0] * m0.x;
            float c1 = sacc[j][1] * m0.y;
            float c2 = sacc[j][2] * m1.x;
            float c3 = sacc[j][3] * m1.y;
            racc0 += fabsf(c0) + fabsf(c1);
            racc1 += fabsf(c2) + fabsf(c3);

            float x00 = __shfl_sync(0xffffffffu, c0, s0l, 4);
            float x01 = __shfl_sync(0xffffffffu, c1, s0l, 4);
            float x20 = __shfl_sync(0xffffffffu, c0, s2l, 4);
            float x21 = __shfl_sync(0xffffffffu, c1, s2l, 4);
            float y00 = __shfl_sync(0xffffffffu, c2, s0l, 4);
            float y01 = __shfl_sync(0xffffffffu, c3, s0l, 4);
            float y20 = __shfl_sync(0xffffffffu, c2, s2l, 4);
            float y21 = __shfl_sync(0xffffffffu, c3, s2l, 4);
            uint32_t a0 = f2tf32(od ? x01 : x00);
            uint32_t a1 = f2tf32(od ? y01 : y00);
            uint32_t a2 = f2tf32(od ? x21 : x20);
            uint32_t a3 = f2tf32(od ? y21 : y20);

            const int vr0 = (8 * j + tig) * VP + gid;
            const int vr1 = (8 * j + 4 + tig) * VP + gid;
            #pragma unroll
            for (int db = 0; db < 8; db++)
                mma_tf32(oacc[db], a0, a1, a2, a3,
                         vsW[vr0 + 8 * db], vsW[vr1 + 8 * db]);
            m0 = n0; m1 = n1;
        }

        // ---- store next-V (cvt once) ----
        if (pf) {
            #pragma unroll
            for (int i = 0; i < 4; i++) {
                uint4 y;
                y.x = f2tf32(xv[i].x); y.y = f2tf32(xv[i].y);
                y.z = f2tf32(xv[i].z); y.w = f2tf32(xv[i].w);
                *(uint4*)(nv + (size_t)((sr + i * 16) * VP + sc4) * 4) = y;
            }
        }
        __syncthreads();
    }

    // ---- warp-local row abs-sums (warp owns full rows) ----
    racc0 += __shfl_xor_sync(0xffffffffu, racc0, 1);
    racc0 += __shfl_xor_sync(0xffffffffu, racc0, 2);
    racc1 += __shfl_xor_sync(0xffffffffu, racc1, 1);
    racc1 += __shfl_xor_sync(0xffffffffu, racc1, 2);
    const float rinv0 = 1.0f / fmaxf(racc0, 1.0f);
    const float rinv1 = 1.0f / fmaxf(racc1, 1.0f);

    float* or0 = og + (size_t)(q0 + mbase + gid) * Dc;
    float* or1 = or0 + (size_t)8 * Dc;
    #pragma unroll
    for (int db = 0; db < 8; db++) {
        const int col = 8 * db + 2 * tig;
        float2 y0, y1;
        y0.x = oacc[db][0] * rinv0; y0.y = oacc[db][1] * rinv0;
        y1.x = oacc[db][2] * rinv1; y1.y = oacc[db][3] * rinv1;
        *(float2*)(or0 + col) = y0;
        *(float2*)(or1 + col) = y1;
    }
}

extern "C" void kernel_launch(void* const* d_in, const int* in_sizes, int n_in,
                              void* d_out, int out_size)
{
    (void)in_sizes; (void)n_in; (void)out_size;
    const float* q    = (const float*)d_in[0];
    const float* k    = (const float*)d_in[1];
    const float* v    = (const float*)d_in[2];
    const float* mask = (const float*)d_in[3];
    float* o = (float*)d_out;

    cudaFuncSetAttribute(fra_mma5_kernel,
                         cudaFuncAttributeMaxDynamicSharedMemorySize, SM_TOT);

    dim3 grid(Sc / BM, Bc * Hc);   // (16, 32)
    fra_mma5_kernel<<<grid, 256, SM_TOT>>>(q, k, v, mask, o);
}

// round 9
// speedup vs baseline: 1.9582x; 1.9582x over previous
#include <cuda_runtime.h>
#include <cuda_fp16.h>
#include <cstdint>
#include <cstddef>

// Problem shape (fixed)
#define Bc 2
#define Hc 16
#define Sc 2048
#define Dc 64
#define NELEM  (Bc * Hc * Sc * Dc)   // 4194304
#define NELEM2 (NELEM / 2)

// Tiling
#define BM 128            // q rows per CTA
#define BK 64             // keys per tile
#define NT (Sc / BK)      // 32 tiles
#define PH 72             // fp16 smem pitch (halfs); 144B rows -> conflict-free ldmatrix

// SMEM layout (bytes)
#define SM_Q   0
#define SMQB   (BM * PH * 2)          // 18432
#define KVB    (BK * PH * 2)          // 9216 (one K or V tile)
#define STB    (2 * KVB)              // 18432 per stage (K + V)
#define NSTG   3
#define SM_TOT (SMQB + NSTG * STB)    // 73728

// fp16 scratch (pre-converted inputs)
__device__ __align__(16) __half2 QH[NELEM2];
__device__ __align__(16) __half2 KH[NELEM2];
__device__ __align__(16) __half2 VH[NELEM2];

__global__ void cvt_f2h(const float2* __restrict__ q,
                        const float2* __restrict__ k,
                        const float2* __restrict__ v)
{
    int i = blockIdx.x * 256 + threadIdx.x;
    float2 a = q[i]; QH[i] = __floats2half2_rn(a.x, a.y);
    float2 b = k[i]; KH[i] = __floats2half2_rn(b.x, b.y);
    float2 c = v[i]; VH[i] = __floats2half2_rn(c.x, c.y);
}

static __device__ __forceinline__ uint32_t smem_u32(const void* p) {
    uint32_t a;
    asm("{ .reg .u64 t; cvta.to.shared.u64 t, %1; cvt.u32.u64 %0, t; }"
        : "=r"(a) : "l"(p));
    return a;
}
static __device__ __forceinline__ void mma_f16(float c[4],
                                               uint32_t a0, uint32_t a1, uint32_t a2, uint32_t a3,
                                               uint32_t b0, uint32_t b1) {
    asm volatile(
        "mma.sync.aligned.m16n8k16.row.col.f32.f16.f16.f32 "
        "{%0,%1,%2,%3}, {%4,%5,%6,%7}, {%8,%9}, {%0,%1,%2,%3};"
        : "+f"(c[0]), "+f"(c[1]), "+f"(c[2]), "+f"(c[3])
        : "r"(a0), "r"(a1), "r"(a2), "r"(a3), "r"(b0), "r"(b1));
}
static __device__ __forceinline__ void ldsm4(uint32_t& r0, uint32_t& r1,
                                             uint32_t& r2, uint32_t& r3, uint32_t a) {
    asm volatile("ldmatrix.sync.aligned.m8n8.x4.shared.b16 {%0,%1,%2,%3}, [%4];"
                 : "=r"(r0), "=r"(r1), "=r"(r2), "=r"(r3) : "r"(a));
}
static __device__ __forceinline__ void ldsm4t(uint32_t& r0, uint32_t& r1,
                                              uint32_t& r2, uint32_t& r3, uint32_t a) {
    asm volatile("ldmatrix.sync.aligned.m8n8.x4.trans.shared.b16 {%0,%1,%2,%3}, [%4];"
                 : "=r"(r0), "=r"(r1), "=r"(r2), "=r"(r3) : "r"(a));
}
static __device__ __forceinline__ void cp16(uint32_t dst, const void* src) {
    asm volatile("cp.async.cg.shared.global [%0], [%1], 16;"
                 :: "r"(dst), "l"(src) : "memory");
}

__global__ __launch_bounds__(256, 2)
void fra_f16_kernel(const float* __restrict__ mask, float* __restrict__ o)
{
    extern __shared__ char smem[];
    const uint32_t sb = smem_u32(smem);
    const int tid  = threadIdx.x;
    const int lane = tid & 31;
    const int wid  = tid >> 5;
    const int gid  = lane >> 2;
    const int tig  = lane & 3;
    const int mbase = wid * 16;            // warp's 16-row strip
    const int bh = blockIdx.y;
    const int q0 = blockIdx.x * BM;

    const __half* qh = (const __half*)QH + (size_t)bh * Sc * Dc;
    const __half* kh = (const __half*)KH + (size_t)bh * Sc * Dc;
    const __half* vh = (const __half*)VH + (size_t)bh * Sc * Dc;
    const float*  mg = mask + (size_t)bh * Sc * Sc;
    float*        og = o    + (size_t)bh * Sc * Dc;

    // ---- prologue: cp.async Q + tile0 (group A), tile1 (group B) ----
    {
        // Q: 128 rows x 8 chunks of 16B
        #pragma unroll
        for (int i = 0; i < 4; i++) {
            int fi = tid + i * 256;
            int r = fi >> 3, c8 = fi & 7;
            cp16(sb + SM_Q + (uint32_t)(r * PH + c8 * 8) * 2,
                 qh + (size_t)(q0 + r) * Dc + c8 * 8);
        }
        // tile 0 K/V: 64 rows x 8 chunks each
        #pragma unroll
        for (int i = 0; i < 2; i++) {
            int fi = tid + i * 256;
            int r = fi >> 3, c8 = fi & 7;
            cp16(sb + SMQB + (uint32_t)(r * PH + c8 * 8) * 2,
                 kh + (size_t)r * Dc + c8 * 8);
            cp16(sb + SMQB + KVB + (uint32_t)(r * PH + c8 * 8) * 2,
                 vh + (size_t)r * Dc + c8 * 8);
        }
        asm volatile("cp.async.commit_group;" ::: "memory");
        #pragma unroll
        for (int i = 0; i < 2; i++) {
            int fi = tid + i * 256;
            int r = fi >> 3, c8 = fi & 7;
            cp16(sb + SMQB + STB + (uint32_t)(r * PH + c8 * 8) * 2,
                 kh + (size_t)(BK + r) * Dc + c8 * 8);
            cp16(sb + SMQB + STB + KVB + (uint32_t)(r * PH + c8 * 8) * 2,
                 vh + (size_t)(BK + r) * Dc + c8 * 8);
        }
        asm volatile("cp.async.commit_group;" ::: "memory");
    }

    // per-lane fragment address components
    const int qrow  = (lane & 7) + 8 * ((lane >> 3) & 1);   // A / V-trans row pattern
    const int qcol8 = 8 * (lane >> 4);
    const int krow  = (lane & 7) + 8 * (lane >> 4);          // K B-frag row pattern
    const int kcolb = 8 * ((lane >> 3) & 1);
    const uint32_t aQ = sb + SM_Q + (uint32_t)((mbase + qrow) * PH + qcol8) * 2;

    float oacc[8][4];
    #pragma unroll
    for (int d = 0; d < 8; d++)
        #pragma unroll
        for (int r = 0; r < 4; r++) oacc[d][r] = 0.0f;
    float racc0 = 0.0f, racc1 = 0.0f;

    const float* mr0 = mg + (size_t)(q0 + mbase + gid) * Sc;
    const float* mr1 = mr0 + (size_t)8 * Sc;

    for (int tt = 0; tt < NT; tt++) {
        const int t = tt * BK;
        // issue tile tt+2 into stage (tt+2)%3 (freed by end-barrier of iter tt-1)
        if (tt + 2 < NT) {
            const uint32_t stb = sb + SMQB + (uint32_t)((tt + 2) % NSTG) * STB;
            #pragma unroll
            for (int i = 0; i < 2; i++) {
                int fi = tid + i * 256;
                int r = fi >> 3, c8 = fi & 7;
                cp16(stb + (uint32_t)(r * PH + c8 * 8) * 2,
                     kh + (size_t)(t + 2 * BK + r) * Dc + c8 * 8);
                cp16(stb + KVB + (uint32_t)(r * PH + c8 * 8) * 2,
                     vh + (size_t)(t + 2 * BK + r) * Dc + c8 * 8);
            }
            asm volatile("cp.async.commit_group;" ::: "memory");
            asm volatile("cp.async.wait_group 2;" ::: "memory");
        } else if (tt + 1 < NT) {
            asm volatile("cp.async.wait_group 1;" ::: "memory");
        } else {
            asm volatile("cp.async.wait_group 0;" ::: "memory");
        }
        __syncthreads();   // tile tt visible to all warps

        const uint32_t kbs = sb + SMQB + (uint32_t)(tt % NSTG) * STB;
        const uint32_t vbs = kbs + KVB;

        // ---- GEMM1: S(16x64) = Q @ K^T, fp16 m16n8k16, 4 k-steps ----
        float sacc[8][4];
        #pragma unroll
        for (int j = 0; j < 8; j++)
            #pragma unroll
            for (int r = 0; r < 4; r++) sacc[j][r] = 0.0f;

        #pragma unroll
        for (int kk = 0; kk < 4; kk++) {
            uint32_t a0, a1, a2, a3;
            ldsm4(a0, a1, a2, a3, aQ + (uint32_t)kk * 32);
            #pragma unroll
            for (int p = 0; p < 4; p++) {
                uint32_t b0, b1, b2, b3;
                ldsm4(b0, b1, b2, b3,
                      kbs + (uint32_t)((16 * p + krow) * PH + kk * 16 + kcolb) * 2);
                mma_f16(sacc[2 * p],     a0, a1, a2, a3, b0, b1);
                mma_f16(sacc[2 * p + 1], a0, a1, a2, a3, b2, b3);
            }
        }

        // ---- mask + abs-sum + pack P-fragments (C-frag == fp16 A-frag layout) ----
        uint32_t ph[8][2];
        #pragma unroll
        for (int j = 0; j < 8; j++) {
            const int col = 8 * j + 2 * tig;
            float2 m0 = *(const float2*)(mr0 + t + col);
            float2 m1 = *(const float2*)(mr1 + t + col);
            float s0 = sacc[j][0] * m0.x;
            float s1 = sacc[j][1] * m0.y;
            float s2 = sacc[j][2] * m1.x;
            float s3 = sacc[j][3] * m1.y;
            racc0 += fabsf(s0) + fabsf(s1);
            racc1 += fabsf(s2) + fabsf(s3);
            __half2 p0 = __floats2half2_rn(s0, s1);
            __half2 p1 = __floats2half2_rn(s2, s3);
            ph[j][0] = *(uint32_t*)&p0;
            ph[j][1] = *(uint32_t*)&p1;
        }

        // ---- GEMM2: O(16x64) += P @ V, B-frags via ldmatrix.trans on V ----
        #pragma unroll
        for (int kk = 0; kk < 4; kk++) {
            uint32_t a0 = ph[2 * kk][0];
            uint32_t a1 = ph[2 * kk][1];
            uint32_t a2 = ph[2 * kk + 1][0];
            uint32_t a3 = ph[2 * kk + 1][1];
            #pragma unroll
            for (int p = 0; p < 4; p++) {
                uint32_t b0, b1, b2, b3;
                ldsm4t(b0, b1, b2, b3,
                       vbs + (uint32_t)((16 * kk + qrow) * PH + 16 * p + qcol8) * 2);
                mma_f16(oacc[2 * p],     a0, a1, a2, a3, b0, b1);
                mma_f16(oacc[2 * p + 1], a0, a1, a2, a3, b2, b3);
            }
        }
        __syncthreads();   // stage (tt)%3 free for reuse at iter tt+1's issue
    }

    // ---- warp-local row abs-sums (warp owns full rows) ----
    racc0 += __shfl_xor_sync(0xffffffffu, racc0, 1);
    racc0 += __shfl_xor_sync(0xffffffffu, racc0, 2);
    racc1 += __shfl_xor_sync(0xffffffffu, racc1, 1);
    racc1 += __shfl_xor_sync(0xffffffffu, racc1, 2);
    const float rinv0 = 1.0f / fmaxf(racc0, 1.0f);
    const float rinv1 = 1.0f / fmaxf(racc1, 1.0f);

    float* or0 = og + (size_t)(q0 + mbase + gid) * Dc;
    float* or1 = or0 + (size_t)8 * Dc;
    #pragma unroll
    for (int db = 0; db < 8; db++) {
        const int col = 8 * db + 2 * tig;
        float2 y0, y1;
        y0.x = oacc[db][0] * rinv0; y0.y = oacc[db][1] * rinv0;
        y1.x = oacc[db][2] * rinv1; y1.y = oacc[db][3] * rinv1;
        *(float2*)(or0 + col) = y0;
        *(float2*)(or1 + col) = y1;
    }
}

extern "C" void kernel_launch(void* const* d_in, const int* in_sizes, int n_in,
                              void* d_out, int out_size)
{
    (void)in_sizes; (void)n_in; (void)out_size;
    const float* q    = (const float*)d_in[0];
    const float* k    = (const float*)d_in[1];
    const float* v    = (const float*)d_in[2];
    const float* mask = (const float*)d_in[3];
    float* o = (float*)d_out;

    // pre-convert q/k/v to fp16 scratch
    cvt_f2h<<<NELEM2 / 256, 256>>>((const float2*)q, (const float2*)k, (const float2*)v);

    cudaFuncSetAttribute(fra_f16_kernel,
                         cudaFuncAttributeMaxDynamicSharedMemorySize, SM_TOT);
    dim3 grid(Sc / BM, Bc * Hc);   // (16, 32)
    fra_f16_kernel<<<grid, 256, SM_TOT>>>(mask, o);
}